// round 12
// baseline (speedup 1.0000x reference)
#include <cuda_runtime.h>
#include <cuda_bf16.h>
#include <cstdint>
#include <math.h>

#define B_      256
#define FERD    2048
#define LMD     256
#define NC      7
#define KNN     8
#define NPAIR   (B_*KNN)     // 2048
#define EPSV    1e-8f

__device__ __forceinline__ uint32_t smem_to_u32(const void* p) {
    uint32_t a;
    asm("{ .reg .u64 t; cvta.to.shared.u64 t, %1; cvt.u32.u64 %0, t; }" : "=r"(a) : "l"(p));
    return a;
}
#define MBARRIER_INIT(mbar, count) \
    asm volatile("mbarrier.init.shared.b64 [%0], %1;" \
        :: "r"((uint32_t)(mbar)), "r"((uint32_t)(count)) : "memory")
#define MBARRIER_EXPECT_TX(mbar, bytes) \
    asm volatile("mbarrier.arrive.expect_tx.shared.b64 _, [%0], %1;" \
        :: "r"((uint32_t)(mbar)), "r"((uint32_t)(bytes)) : "memory")
#define MBARRIER_WAIT_PARITY(mbar_smem_addr, phase_parity) do { \
    uint32_t _mbar = (uint32_t)(mbar_smem_addr); \
    uint32_t _parity = (uint32_t)(phase_parity); \
    uint32_t _done; \
    asm volatile("{\n\t.reg .pred p;\n\t" \
        "mbarrier.try_wait.parity.acquire.cta.shared::cta.b64 p, [%1], %2;\n\t" \
        "selp.b32 %0, 1, 0, p;\n\t}" \
        : "=r"(_done) : "r"(_mbar), "r"(_parity) : "memory"); \
    if (!_done) { \
        asm volatile("{\n\t.reg .pred P1;\n\t" \
            "WAIT_LOOP_%=:\n\t" \
            "mbarrier.try_wait.parity.acquire.cta.shared::cta.b64 P1, [%0], %1, 0x989680;\n\t" \
            "@P1 bra.uni WAIT_DONE_%=;\n\t" \
            "bra.uni WAIT_LOOP_%=;\n\t" \
            "WAIT_DONE_%=:\n\t}" \
            :: "r"(_mbar), "r"(_parity) : "memory"); \
    } \
} while(0)

// ====================================================================
// scratch (no allocations allowed)
// ====================================================================
struct __align__(16) Scratch {
    __nv_bfloat16 w_in_b[FERD*FERD];
    __nv_bfloat16 w1_b  [1024*FERD];
    __nv_bfloat16 w2_b  [512*1024];
    __nv_bfloat16 xhi_fer[B_*FERD];
    __nv_bfloat16 xlo_fer[B_*FERD];
    __nv_bfloat16 l_win_b[LMD*LMD];
    __nv_bfloat16 l_w1_b [128*LMD];
    __nv_bfloat16 xhi_lm [B_*LMD];
    __nv_bfloat16 xlo_lm [B_*LMD];
    __nv_bfloat16 feats_fer_b[B_*FERD];
    __nv_bfloat16 feats_lm_b [B_*LMD];
    __nv_bfloat16 H_fer_b[NPAIR*1024];
    __nv_bfloat16 H_lm_b [NPAIR*128];
    __nv_bfloat16 l_w2_pad_b[128*128];
    float         l_b2_pad[128];
    float G_fer[B_*B_], P_fer[B_*B_];
    float G_lm [B_*B_], P_lm [B_*B_];
    float A_lm [B_*128],  Bm_lm [B_*128];
    float H2_lm [NPAIR*128];
    float score_fer[NPAIR], score_lm[NPAIR];
    int   nbr_fer[NPAIR], nbr_lm[NPAIR];
    float Cpart[2*1024*1024];      // FER-chain split-K partials
    float CpartSim[16*B_*B_];      // sim-chain partials (overlapped streams)
};
__device__ Scratch g_s;

// ====================================================================
// conversions split in two so only w_in + x precede the FER chain
// ====================================================================
#define CN1 (FERD*FERD)
#define CN2 (1024*FERD)
#define CN3 (512*1024)
#define CN4 (B_*FERD)
#define CN5 (LMD*LMD)
#define CN6 (128*LMD)
#define CN7 (B_*LMD)

__device__ __forceinline__ void cvt4(const float* src, __nv_bfloat16* dst,
                                     __nv_bfloat16* lo, int off) {
    float4 v = *(const float4*)(src + off);
    __nv_bfloat16 h0 = __float2bfloat16(v.x), h1 = __float2bfloat16(v.y);
    __nv_bfloat16 h2 = __float2bfloat16(v.z), h3 = __float2bfloat16(v.w);
    *(__nv_bfloat162*)(dst + off)     = __nv_bfloat162(h0, h1);
    *(__nv_bfloat162*)(dst + off + 2) = __nv_bfloat162(h2, h3);
    if (lo) {
        *(__nv_bfloat162*)(lo + off) = __nv_bfloat162(
            __float2bfloat16(v.x - __bfloat162float(h0)),
            __float2bfloat16(v.y - __bfloat162float(h1)));
        *(__nv_bfloat162*)(lo + off + 2) = __nv_bfloat162(
            __float2bfloat16(v.z - __bfloat162float(h2)),
            __float2bfloat16(v.w - __bfloat162float(h3)));
    }
}

// A: w_in + x_fer(hi/lo) + x_lm(hi/lo)
__global__ void convertA(const float* __restrict__ fw_in, const float* __restrict__ fx,
                         const float* __restrict__ lx, Scratch* s) {
    int total4 = (CN1 + CN4 + CN7) / 4;
    for (int i = blockIdx.x * blockDim.x + threadIdx.x; i < total4;
         i += gridDim.x * blockDim.x) {
        int j = i * 4;
        if      (j < CN1)       cvt4(fw_in, s->w_in_b, nullptr, j);
        else if (j < CN1 + CN4) cvt4(fx, s->xhi_fer, s->xlo_fer, j - CN1);
        else                    cvt4(lx, s->xhi_lm, s->xlo_lm, j - CN1 - CN4);
    }
}

// B: w1, w2, l_win, l_w1, l_w2 pad, l_b2 pad
__global__ void convertB(const float* __restrict__ fw1, const float* __restrict__ fw2,
                         const float* __restrict__ lwin, const float* __restrict__ lw1,
                         const float* __restrict__ lw2, const float* __restrict__ lb2,
                         Scratch* s) {
    int total4 = (CN2 + CN3 + CN5 + CN6) / 4;
    for (int i = blockIdx.x * blockDim.x + threadIdx.x; i < total4;
         i += gridDim.x * blockDim.x) {
        int j = i * 4;
        if      (j < CN2)             cvt4(fw1, s->w1_b, nullptr, j);
        else if (j < CN2 + CN3)       cvt4(fw2, s->w2_b, nullptr, j - CN2);
        else if (j < CN2 + CN3 + CN5) cvt4(lwin, s->l_win_b, nullptr, j - CN2 - CN3);
        else                          cvt4(lw1, s->l_w1_b, nullptr, j - CN2 - CN3 - CN5);
    }
    int t = blockIdx.x * blockDim.x + threadIdx.x;
    if (t < 128 * 128) {
        int r = t >> 7, c = t & 127;
        s->l_w2_pad_b[t] = __float2bfloat16(r < 64 ? lw2[r * 128 + c] : 0.f);
    }
    if (t < 128) s->l_b2_pad[t] = (t < 64) ? lb2[t] : 0.f;
}

// ====================================================================
// bf16 HMMA GEMM, job-fusion (grid.z) + split-K partial output.
// Tile fill via cp.async.bulk (one 128B row per thread) + mbarrier
// complete_tx — 8x fewer LSU issue ops than per-16B cp.async.
// ====================================================================
#define MM_LDS   72                      // elements; 144B row stride
#define MM_ATILE (128*MM_LDS*2)          // 18432
#define MM_BUF   (2*MM_ATILE)            // 36864
#define MM_SMEM  (128 + 3*MM_BUF)        // mbars + 3 stages = 110720
#define MM_TX    (2*128*128)             // actual bytes per stage = 32768

__global__ void __launch_bounds__(256)
gemm_mma(const __nv_bfloat16* __restrict__ A0, const __nv_bfloat16* __restrict__ A1, int lda,
         const __nv_bfloat16* __restrict__ B0, const __nv_bfloat16* __restrict__ B1, int ldb,
         const float* __restrict__ bias, int relu,
         float* __restrict__ Cf0, float* __restrict__ Cf1,
         __nv_bfloat16* __restrict__ Cb0,
         float* __restrict__ Cpart,
         int njobs, int N, int K)
{
    extern __shared__ char smem[];
    uint32_t sb = smem_to_u32(smem);
    const uint32_t STG = sb + 128;
    int tid = threadIdx.x;
    int lane = tid & 31, warp = tid >> 5;
    int wm = warp >> 2, wn = warp & 3;
    int m0 = blockIdx.y * 128, n0 = blockIdx.x * 128;

    int z = blockIdx.z;
    int job   = (njobs == 2) ? (z & 1) : 0;
    int split = (njobs == 2) ? (z >> 1) : z;
    int nsplit = gridDim.z / njobs;
    int Ksplit = K / nsplit;
    int kbase = split * Ksplit;
    int nk = Ksplit >> 6;

    const __nv_bfloat16* A = job ? A1 : A0;
    const __nv_bfloat16* B = job ? B1 : B0;

    if (tid < 3) MBARRIER_INIT(sb + tid * 8, 1);
    __syncthreads();

    // per-thread bulk-copy assignment: one 128B row per thread per stage
    int rowi = tid & 127;
    int isB  = tid >> 7;
    const __nv_bfloat16* rowp = (isB ? B : A) +
        (size_t)((isB ? n0 : m0) + rowi) * (isB ? ldb : lda) + kbase;
    uint32_t dstoff = (uint32_t)(isB * MM_ATILE + rowi * (MM_LDS * 2));

    float acc[4][4][4];
    #pragma unroll
    for (int i = 0; i < 4; i++)
        #pragma unroll
        for (int j = 0; j < 4; j++)
            #pragma unroll
            for (int q = 0; q < 4; q++) acc[i][j][q] = 0.f;

    auto issue = [&](int kt) {
        int st = kt % 3;
        if (tid == 0) MBARRIER_EXPECT_TX(sb + st * 8, MM_TX);
        const __nv_bfloat16* src = rowp + kt * 64;
        asm volatile(
            "cp.async.bulk.shared::cluster.global.mbarrier::complete_tx::bytes "
            "[%0], [%1], 128, [%2];"
            :: "r"(STG + st * MM_BUF + dstoff), "l"(src), "r"(sb + st * 8)
            : "memory");
    };

    issue(0);
    if (nk > 1) issue(1);
    if (nk > 2) issue(2);
    for (int kt = 0; kt < nk; kt++) {
        int st = kt % 3;
        int par = (kt / 3) & 1;
        MBARRIER_WAIT_PARITY(sb + st * 8, par);

        uint32_t aBase = STG + st * MM_BUF;
        uint32_t bBase = aBase + MM_ATILE;
        #pragma unroll
        for (int ks = 0; ks < 4; ks++) {
            int k = ks * 16;
            uint32_t af[4][4];
            #pragma unroll
            for (int im = 0; im < 4; im++) {
                int row = wm * 64 + im * 16 + (lane & 15);
                int kg = (lane >> 4) * 8;
                uint32_t addr = aBase + (uint32_t)(row * MM_LDS + k + kg) * 2;
                asm volatile("ldmatrix.sync.aligned.m8n8.x4.shared.b16 {%0,%1,%2,%3}, [%4];"
                             : "=r"(af[im][0]), "=r"(af[im][1]),
                               "=r"(af[im][2]), "=r"(af[im][3])
                             : "r"(addr));
            }
            uint32_t bf[4][2];
            #pragma unroll
            for (int in = 0; in < 4; in++) {
                int l = lane & 15;
                int n = wn * 32 + in * 8 + (l & 7);
                int kg = (l >> 3) * 8;
                uint32_t addr = bBase + (uint32_t)(n * MM_LDS + k + kg) * 2;
                asm volatile("ldmatrix.sync.aligned.m8n8.x2.shared.b16 {%0,%1}, [%2];"
                             : "=r"(bf[in][0]), "=r"(bf[in][1])
                             : "r"(addr));
            }
            #pragma unroll
            for (int im = 0; im < 4; im++)
                #pragma unroll
                for (int in = 0; in < 4; in++) {
                    asm volatile(
                        "mma.sync.aligned.m16n8k16.row.col.f32.bf16.bf16.f32 "
                        "{%0,%1,%2,%3}, {%4,%5,%6,%7}, {%8,%9}, {%0,%1,%2,%3};"
                        : "+f"(acc[im][in][0]), "+f"(acc[im][in][1]),
                          "+f"(acc[im][in][2]), "+f"(acc[im][in][3])
                        : "r"(af[im][0]), "r"(af[im][1]), "r"(af[im][2]), "r"(af[im][3]),
                          "r"(bf[in][0]), "r"(bf[in][1]));
                }
        }
        __syncthreads();            // all warps done with this stage
        if (kt + 3 < nk) issue(kt + 3);
    }

    if (Cpart) {
        size_t MN = (size_t)gridDim.y * 128 * N;
        float* cp = Cpart + (size_t)z * MN;
        #pragma unroll
        for (int im = 0; im < 4; im++) {
            int m = m0 + wm * 64 + im * 16 + (lane >> 2);
            #pragma unroll
            for (int in = 0; in < 4; in++) {
                int n = n0 + wn * 32 + in * 8 + (lane & 3) * 2;
                *(float2*)(cp + (size_t)m * N + n) =
                    make_float2(acc[im][in][0], acc[im][in][1]);
                *(float2*)(cp + (size_t)(m + 8) * N + n) =
                    make_float2(acc[im][in][2], acc[im][in][3]);
            }
        }
        return;
    }
    float* Cf = job ? Cf1 : Cf0;
    #pragma unroll
    for (int im = 0; im < 4; im++) {
        int m = m0 + wm * 64 + im * 16 + (lane >> 2);
        #pragma unroll
        for (int in = 0; in < 4; in++) {
            int n = n0 + wn * 32 + in * 8 + (lane & 3) * 2;
            float b0 = bias ? bias[n]     : 0.f;
            float b1 = bias ? bias[n + 1] : 0.f;
            float v00 = acc[im][in][0] + b0, v01 = acc[im][in][1] + b1;
            float v10 = acc[im][in][2] + b0, v11 = acc[im][in][3] + b1;
            if (relu) {
                v00 = fmaxf(v00, 0.f); v01 = fmaxf(v01, 0.f);
                v10 = fmaxf(v10, 0.f); v11 = fmaxf(v11, 0.f);
            }
            if (Cb0) {
                *(__nv_bfloat162*)(Cb0 + (size_t)m * N + n) =
                    __floats2bfloat162_rn(v00, v01);
                *(__nv_bfloat162*)(Cb0 + (size_t)(m + 8) * N + n) =
                    __floats2bfloat162_rn(v10, v11);
            } else {
                *(float2*)(Cf + (size_t)m * N + n)       = make_float2(v00, v01);
                *(float2*)(Cf + (size_t)(m + 8) * N + n) = make_float2(v10, v11);
            }
        }
    }
}

// ====================================================================
// split-K reduce (fully unrolled predicated split loop)
// ====================================================================
__global__ void reduce_parts(const float* __restrict__ part, int nsplit, int njobs,
                             long MN, int N,
                             const float* __restrict__ bias0,
                             const float* __restrict__ bias1, int relu,
                             float* __restrict__ of0, float* __restrict__ of1,
                             __nv_bfloat16* __restrict__ ob0) {
    long MN4 = MN >> 2;
    long total = (long)njobs * MN4;
    for (long idx = blockIdx.x * (long)blockDim.x + threadIdx.x; idx < total;
         idx += (long)gridDim.x * blockDim.x) {
        int  job = (int)(idx / MN4);
        long e4  = idx - (long)job * MN4;
        float4 acc[8];
        #pragma unroll
        for (int sp = 0; sp < 8; sp++) {
            acc[sp] = make_float4(0.f, 0.f, 0.f, 0.f);
            if (sp < nsplit)
                acc[sp] = *((const float4*)(part + ((size_t)(sp * njobs + job)) * MN) + e4);
        }
        float4 s;
        s.x = ((acc[0].x + acc[1].x) + (acc[2].x + acc[3].x)) +
              ((acc[4].x + acc[5].x) + (acc[6].x + acc[7].x));
        s.y = ((acc[0].y + acc[1].y) + (acc[2].y + acc[3].y)) +
              ((acc[4].y + acc[5].y) + (acc[6].y + acc[7].y));
        s.z = ((acc[0].z + acc[1].z) + (acc[2].z + acc[3].z)) +
              ((acc[4].z + acc[5].z) + (acc[6].z + acc[7].z));
        s.w = ((acc[0].w + acc[1].w) + (acc[2].w + acc[3].w)) +
              ((acc[4].w + acc[5].w) + (acc[6].w + acc[7].w));
        const float* bias = job ? bias1 : bias0;
        if (bias) {
            int col = (int)((e4 * 4) % N);
            s.x += bias[col]; s.y += bias[col + 1]; s.z += bias[col + 2]; s.w += bias[col + 3];
        }
        if (relu) {
            s.x = fmaxf(s.x, 0.f); s.y = fmaxf(s.y, 0.f);
            s.z = fmaxf(s.z, 0.f); s.w = fmaxf(s.w, 0.f);
        }
        if (job == 0 && ob0) {
            *(__nv_bfloat162*)(ob0 + e4 * 4)     = __floats2bfloat162_rn(s.x, s.y);
            *(__nv_bfloat162*)(ob0 + e4 * 4 + 2) = __floats2bfloat162_rn(s.z, s.w);
        } else {
            float* o = job ? of1 : of0;
            *((float4*)o + e4) = s;
        }
    }
}

// ====================================================================
// top-8: 512 warps; warp<256 -> FER matrices, else LM
// ====================================================================
__global__ void topk8_warp(const float* __restrict__ Gf, const float* __restrict__ Pf,
                           int* __restrict__ nbrf,
                           const float* __restrict__ Gl, const float* __restrict__ Pl,
                           int* __restrict__ nbrl) {
    int w = blockIdx.x * (blockDim.x >> 5) + (threadIdx.x >> 5);
    int lane = threadIdx.x & 31;
    const float* G; const float* P; int* nbr; int row;
    if (w < B_) { G = Gf; P = Pf; nbr = nbrf; row = w; }
    else        { G = Gl; P = Pl; nbr = nbrl; row = w - B_; }
    float v[8];
    #pragma unroll
    for (int t = 0; t < 8; t++) {
        int j = lane + t * 32;
        if (j == row) { v[t] = -1e30f; continue; }
        float g  = G[(size_t)row * B_ + j];
        float p1 = P[(size_t)row * B_ + j];
        float p2 = P[(size_t)j * B_ + row];
        float dg = G[(size_t)j * B_ + j];
        float dp = P[(size_t)j * B_ + j];
        v[t] = (g + p1 + p2) * rsqrtf(dg + 2.f * dp);
    }
    for (int t = 0; t < KNN; t++) {
        float bv = -1e30f; int bi = 0x7fffffff;
        #pragma unroll
        for (int q = 0; q < 8; q++) {
            int j = lane + q * 32;
            if (v[q] > bv || (v[q] == bv && j < bi)) { bv = v[q]; bi = j; }
        }
        #pragma unroll
        for (int o = 16; o; o >>= 1) {
            float ov = __shfl_xor_sync(0xffffffffu, bv, o);
            int   oi = __shfl_xor_sync(0xffffffffu, bi, o);
            if (ov > bv || (ov == bv && oi < bi)) { bv = ov; bi = oi; }
        }
        if (lane == 0) nbr[row * KNN + t] = bi;
        if (lane == (bi & 31)) v[bi >> 5] = -1e30f;
    }
}

// ====================================================================
// build H for both branches (FER sums A/Bm split-K partials inline)
// ====================================================================
__global__ void build_h_all(const float* __restrict__ part, const float* __restrict__ f_b1,
                            const int* __restrict__ nbrf, __nv_bfloat16* __restrict__ Hf,
                            const float* __restrict__ A_lm, const float* __restrict__ Bm_lm,
                            const float* __restrict__ l_b1, const int* __restrict__ nbrl,
                            __nv_bfloat16* __restrict__ Hl) {
    int blk = blockIdx.x;
    if (blk < NPAIR) {
        const long MN = (long)B_ * 1024;
        int pair = blk;
        int i = pair >> 3;
        int j = nbrf[pair];
        int k = threadIdx.x * 4;
        const float4* a0 = (const float4*)(part + 0 * MN + (size_t)i * 1024 + k);
        const float4* a1 = (const float4*)(part + 2 * MN + (size_t)i * 1024 + k);
        const float4* b0 = (const float4*)(part + 1 * MN + (size_t)j * 1024 + k);
        const float4* b1p = (const float4*)(part + 3 * MN + (size_t)j * 1024 + k);
        float4 va0 = *a0, va1 = *a1, vb0 = *b0, vb1 = *b1p;
        float4 bb = *(const float4*)(f_b1 + k);
        float h0 = fmaxf(va0.x + va1.x + vb0.x + vb1.x + bb.x, 0.f);
        float h1 = fmaxf(va0.y + va1.y + vb0.y + vb1.y + bb.y, 0.f);
        float h2 = fmaxf(va0.z + va1.z + vb0.z + vb1.z + bb.z, 0.f);
        float h3 = fmaxf(va0.w + va1.w + vb0.w + vb1.w + bb.w, 0.f);
        __nv_bfloat16* hr = Hf + (size_t)pair * 1024 + k;
        *(__nv_bfloat162*)(hr)     = __floats2bfloat162_rn(h0, h1);
        *(__nv_bfloat162*)(hr + 2) = __floats2bfloat162_rn(h2, h3);
    } else {
        int pair = blk - NPAIR;
        int i = pair >> 3;
        int j = nbrl[pair];
        int t = threadIdx.x;
        if (t < 32) {
            int k = t * 4;
            float4 va = *(const float4*)(A_lm + (size_t)i * 128 + k);
            float4 vb = *(const float4*)(Bm_lm + (size_t)j * 128 + k);
            float4 bb = *(const float4*)(l_b1 + k);
            float h0 = fmaxf(va.x + vb.x + bb.x, 0.f);
            float h1 = fmaxf(va.y + vb.y + bb.y, 0.f);
            float h2 = fmaxf(va.z + vb.z + bb.z, 0.f);
            float h3 = fmaxf(va.w + vb.w + bb.w, 0.f);
            __nv_bfloat16* hr = Hl + (size_t)pair * 128 + k;
            *(__nv_bfloat162*)(hr)     = __floats2bfloat162_rn(h0, h1);
            *(__nv_bfloat162*)(hr + 2) = __floats2bfloat162_rn(h2, h3);
        }
    }
}

// ====================================================================
// fused score for both branches (FER sums H2 partials inline)
// ====================================================================
__global__ void score_fused(const float* __restrict__ fpart, const float* __restrict__ f_b2,
                            const float* __restrict__ f_w3, const float* __restrict__ f_b3,
                            float* __restrict__ sf,
                            const float* __restrict__ lH2, const float* __restrict__ l_w3,
                            const float* __restrict__ l_b3, float* __restrict__ sl) {
    int w = blockIdx.x * (blockDim.x >> 5) + (threadIdx.x >> 5);
    int lane = threadIdx.x & 31;
    float s = 0.f;
    if (w < NPAIR) {
        const long MN = (long)NPAIR * 512;
        const float* h0 = fpart + (size_t)w * 512;
        const float* h1 = fpart + MN + (size_t)w * 512;
        #pragma unroll
        for (int q = 0; q < 16; q++) {
            int k = lane + q * 32;
            float h = fmaxf(h0[k] + h1[k] + f_b2[k], 0.f);
            s += h * (f_w3[k] - f_w3[512 + k]);
        }
        #pragma unroll
        for (int o = 16; o; o >>= 1) s += __shfl_xor_sync(0xffffffffu, s, o);
        if (lane == 0) {
            s += f_b3[0] - f_b3[1];
            sf[w] = 1.f / (1.f + expf(-s));
        }
    } else {
        int pair = w - NPAIR;
        const float* h = lH2 + (size_t)pair * 128;
        #pragma unroll
        for (int q = 0; q < 2; q++) {
            int k = lane + q * 32;
            s += h[k] * (l_w3[k] - l_w3[64 + k]);
        }
        #pragma unroll
        for (int o = 16; o; o >>= 1) s += __shfl_xor_sync(0xffffffffu, s, o);
        if (lane == 0) {
            s += l_b3[0] - l_b3[1];
            sl[pair] = 1.f / (1.f + expf(-s));
        }
    }
}

// ====================================================================
// softmax(logits), normalize weights, combine with bank
// ====================================================================
__global__ void combine(const float* __restrict__ logits, const int* __restrict__ idx,
                        const float* __restrict__ bank,
                        const float* __restrict__ sf, const float* __restrict__ sl,
                        const int* __restrict__ nbrf, const int* __restrict__ nbrl,
                        float* __restrict__ out) {
    __shared__ float p[B_][NC];
    __shared__ float colsum[NC];
    int i = threadIdx.x;
    const float* lr = logits + i * NC;
    float m = lr[0];
    #pragma unroll
    for (int c = 1; c < NC; c++) m = fmaxf(m, lr[c]);
    float e[NC]; float ssum = 0.f;
    #pragma unroll
    for (int c = 0; c < NC; c++) { e[c] = expf(lr[c] - m); ssum += e[c]; }
    float invs = 1.f / ssum;
    #pragma unroll
    for (int c = 0; c < NC; c++) p[i][c] = e[c] * invs;
    __syncthreads();
    if (i < NC) {
        float s = 0.f;
        for (int r = 0; r < B_; r++) s += p[r][i];
        colsum[i] = s;
    }
    __syncthreads();
    float Sf = 0.f, Sl = 0.f;
    #pragma unroll
    for (int t = 0; t < KNN; t++) { Sf += sf[i * KNN + t]; Sl += sl[i * KNN + t]; }
    float df = 1.f / (Sf + EPSV), dl = 1.f / (Sl + EPSV);
    float tf[NC], tl[NC];
    #pragma unroll
    for (int c = 0; c < NC; c++) { tf[c] = 0.f; tl[c] = 0.f; }
    #pragma unroll
    for (int t = 0; t < KNN; t++) {
        int jf = nbrf[i * KNN + t]; float wf = sf[i * KNN + t] * df;
        int jl = nbrl[i * KNN + t]; float wl = sl[i * KNN + t] * dl;
        #pragma unroll
        for (int c = 0; c < NC; c++) {
            tf[c] += wf * p[jf][c];
            tl[c] += wl * p[jl][c];
        }
    }
    float ef = (EPSV / (float)B_) * df;
    float el = (EPSV / (float)B_) * dl;
    #pragma unroll
    for (int c = 0; c < NC; c++) {
        float tgt = 0.5f * (tf[c] + ef * colsum[c]) + 0.5f * (tl[c] + el * colsum[c]);
        out[i * NC + c] = bank[(size_t)idx[i] * NC + c] * 0.9f + tgt * 0.1f;
    }
}

// ====================================================================
// launcher — fork/join DAG (graph-capturable). EVERY side-stream is
// forked from the captured origin stream via an event before use.
// ====================================================================
extern "C" void kernel_launch(void* const* d_in, const int* in_sizes, int n_in,
                              void* d_out, int out_size) {
    const float* fer_x  = (const float*)d_in[0];
    const float* lm_x   = (const float*)d_in[1];
    const float* logits = (const float*)d_in[2];
    const int*   idx    = (const int*)  d_in[3];
    const float* bank   = (const float*)d_in[4];
    const float* f_win  = (const float*)d_in[5];
    const float* f_bin  = (const float*)d_in[6];
    const float* f_w1   = (const float*)d_in[7];
    const float* f_b1   = (const float*)d_in[8];
    const float* f_w2   = (const float*)d_in[9];
    const float* f_b2   = (const float*)d_in[10];
    const float* f_w3   = (const float*)d_in[11];
    const float* f_b3   = (const float*)d_in[12];
    const float* l_win  = (const float*)d_in[13];
    const float* l_bin  = (const float*)d_in[14];
    const float* l_w1   = (const float*)d_in[15];
    const float* l_b1   = (const float*)d_in[16];
    const float* l_w2   = (const float*)d_in[17];
    const float* l_b2   = (const float*)d_in[18];
    const float* l_w3   = (const float*)d_in[19];
    const float* l_b3   = (const float*)d_in[20];
    float* out = (float*)d_out;

    Scratch* s = nullptr;
    cudaGetSymbolAddress((void**)&s, g_s);
    if (!s) return;

    struct Res {
        cudaStream_t s1, s2, s3;
        cudaEvent_t eR, e0, eW, eS2, eT, eL3, eBH, eLH;
        Res() {
            cudaStreamCreateWithFlags(&s1, cudaStreamNonBlocking);
            cudaStreamCreateWithFlags(&s2, cudaStreamNonBlocking);
            cudaStreamCreateWithFlags(&s3, cudaStreamNonBlocking);
            cudaEventCreateWithFlags(&eR,  cudaEventDisableTiming);
            cudaEventCreateWithFlags(&e0,  cudaEventDisableTiming);
            cudaEventCreateWithFlags(&eW,  cudaEventDisableTiming);
            cudaEventCreateWithFlags(&eS2, cudaEventDisableTiming);
            cudaEventCreateWithFlags(&eT,  cudaEventDisableTiming);
            cudaEventCreateWithFlags(&eL3, cudaEventDisableTiming);
            cudaEventCreateWithFlags(&eBH, cudaEventDisableTiming);
            cudaEventCreateWithFlags(&eLH, cudaEventDisableTiming);
            cudaFuncSetAttribute(gemm_mma,
                cudaFuncAttributeMaxDynamicSharedMemorySize, MM_SMEM);
        }
    };
    static Res r;
    cudaStream_t L = 0;

    // capture-root fork point: s2 must join the graph BEFORE any launch on it
    cudaEventRecord(r.eR, L);
    cudaStreamWaitEvent(r.s2, r.eR, 0);
    convertB<<<256, 256, 0, r.s2>>>(f_w1, f_w2, l_win, l_w1, l_w2, l_b2, s);
    cudaEventRecord(r.eW, r.s2);

    // convertA on origin stream (x + w_in)
    convertA<<<512, 256, 0, L>>>(f_win, fer_x, lm_x, s);
    cudaEventRecord(r.e0, L);

    // branch s1: FER sim -> reduce -> (wait LM sim) -> topk
    cudaStreamWaitEvent(r.s1, r.e0, 0);
    gemm_mma<<<dim3(2, 2, 16), 256, MM_SMEM, r.s1>>>(
        s->xhi_fer, s->xhi_fer, FERD, s->xhi_fer, s->xlo_fer, FERD,
        nullptr, 0, nullptr, nullptr, nullptr, s->CpartSim, 2, B_, FERD);
    reduce_parts<<<128, 256, 0, r.s1>>>(s->CpartSim, 8, 2, (long)B_ * B_, B_,
                                        nullptr, nullptr, 0, s->G_fer, s->P_fer, nullptr);
    // s2 (after convertB): LM sim (needs xhi/xlo_lm from convertA)
    cudaStreamWaitEvent(r.s2, r.e0, 0);
    gemm_mma<<<dim3(2, 2, 2), 256, MM_SMEM, r.s2>>>(
        s->xhi_lm, s->xhi_lm, LMD, s->xhi_lm, s->xlo_lm, LMD,
        nullptr, 0, s->G_lm, s->P_lm, nullptr, nullptr, 2, B_, LMD);
    cudaEventRecord(r.eS2, r.s2);
    cudaStreamWaitEvent(r.s1, r.eS2, 0);
    topk8_warp<<<64, 256, 0, r.s1>>>(s->G_fer, s->P_fer, s->nbr_fer,
                                     s->G_lm, s->P_lm, s->nbr_lm);
    cudaEventRecord(r.eT, r.s1);

    // branch s3: LM MLP (needs convertA outputs + convertB weights)
    cudaStreamWaitEvent(r.s3, r.e0, 0);
    cudaStreamWaitEvent(r.s3, r.eW, 0);
    gemm_mma<<<dim3(LMD/128, B_/128, 1), 256, MM_SMEM, r.s3>>>(
        s->xhi_lm, nullptr, LMD, s->l_win_b, nullptr, LMD,
        l_bin, 0, nullptr, nullptr, s->feats_lm_b, nullptr, 1, LMD, LMD);
    gemm_mma<<<dim3(1, B_/128, 2), 256, MM_SMEM, r.s3>>>(
        s->feats_lm_b, s->feats_lm_b + 128, LMD, s->l_w1_b, s->l_w1_b + 128, LMD,
        nullptr, 0, s->A_lm, s->Bm_lm, nullptr, nullptr, 2, 128, 128);
    cudaEventRecord(r.eL3, r.s3);

    // main stream: FER MLP (feats -> reduce -> [wait w1] A/Bm)
    gemm_mma<<<dim3(FERD/128, B_/128, 4), 256, MM_SMEM, L>>>(
        s->xhi_fer, nullptr, FERD, s->w_in_b, nullptr, FERD,
        nullptr, 0, nullptr, nullptr, nullptr, s->Cpart, 1, FERD, FERD);
    reduce_parts<<<256, 256, 0, L>>>(s->Cpart, 4, 1, (long)B_ * FERD, FERD,
                                     f_bin, nullptr, 0, nullptr, nullptr, s->feats_fer_b);
    cudaStreamWaitEvent(L, r.eW, 0);
    gemm_mma<<<dim3(1024/128, B_/128, 4), 256, MM_SMEM, L>>>(
        s->feats_fer_b, s->feats_fer_b + 1024, FERD, s->w1_b, s->w1_b + 1024, FERD,
        nullptr, 0, nullptr, nullptr, nullptr, s->Cpart, 2, 1024, 1024);

    // join: build H needs topk (eT), LM A/Bm (eL3), FER A/Bm (in-order on L)
    cudaStreamWaitEvent(L, r.eT, 0);
    cudaStreamWaitEvent(L, r.eL3, 0);
    build_h_all<<<2 * NPAIR, 256, 0, L>>>(s->Cpart, f_b1, s->nbr_fer, s->H_fer_b,
                                          s->A_lm, s->Bm_lm, l_b1, s->nbr_lm, s->H_lm_b);
    cudaEventRecord(r.eBH, L);

    // FER H2 on L; LM H2 on s3 (both depend on build_h)
    gemm_mma<<<dim3(512/128, NPAIR/128, 2), 256, MM_SMEM, L>>>(
        s->H_fer_b, nullptr, 1024, s->w2_b, nullptr, 1024,
        nullptr, 0, nullptr, nullptr, nullptr, s->Cpart, 1, 512, 1024);
    cudaStreamWaitEvent(r.s3, r.eBH, 0);
    gemm_mma<<<dim3(1, NPAIR/128, 1), 256, MM_SMEM, r.s3>>>(
        s->H_lm_b, nullptr, 128, s->l_w2_pad_b, nullptr, 128,
        s->l_b2_pad, 1, s->H2_lm, nullptr, nullptr, nullptr, 1, 128, 128);
    cudaEventRecord(r.eLH, r.s3);

    // join: score needs FER H2 (L in-order) + LM H2 (eLH)
    cudaStreamWaitEvent(L, r.eLH, 0);
    score_fused<<<512, 256, 0, L>>>(s->Cpart, f_b2, f_w3, f_b3, s->score_fer,
                                    s->H2_lm, l_w3, l_b3, s->score_lm);
    combine<<<1, B_, 0, L>>>(logits, idx, bank, s->score_fer, s->score_lm,
                             s->nbr_fer, s->nbr_lm, out);
}

// round 14
// speedup vs baseline: 1.0250x; 1.0250x over previous
#include <cuda_runtime.h>
#include <cuda_bf16.h>
#include <cstdint>
#include <math.h>

#define B_      256
#define FERD    2048
#define LMD     256
#define NC      7
#define KNN     8
#define NPAIR   (B_*KNN)     // 2048
#define EPSV    1e-8f

__device__ __forceinline__ uint32_t smem_to_u32(const void* p) {
    uint32_t a;
    asm("{ .reg .u64 t; cvta.to.shared.u64 t, %1; cvt.u32.u64 %0, t; }" : "=r"(a) : "l"(p));
    return a;
}
#define MBARRIER_INIT(mbar, count) \
    asm volatile("mbarrier.init.shared.b64 [%0], %1;" \
        :: "r"((uint32_t)(mbar)), "r"((uint32_t)(count)) : "memory")
#define MBARRIER_EXPECT_TX(mbar, bytes) \
    asm volatile("mbarrier.arrive.expect_tx.shared.b64 _, [%0], %1;" \
        :: "r"((uint32_t)(mbar)), "r"((uint32_t)(bytes)) : "memory")
#define MBARRIER_WAIT_PARITY(mbar_smem_addr, phase_parity) do { \
    uint32_t _mbar = (uint32_t)(mbar_smem_addr); \
    uint32_t _parity = (uint32_t)(phase_parity); \
    uint32_t _done; \
    asm volatile("{\n\t.reg .pred p;\n\t" \
        "mbarrier.try_wait.parity.acquire.cta.shared::cta.b64 p, [%1], %2;\n\t" \
        "selp.b32 %0, 1, 0, p;\n\t}" \
        : "=r"(_done) : "r"(_mbar), "r"(_parity) : "memory"); \
    if (!_done) { \
        asm volatile("{\n\t.reg .pred P1;\n\t" \
            "WAIT_LOOP_%=:\n\t" \
            "mbarrier.try_wait.parity.acquire.cta.shared::cta.b64 P1, [%0], %1, 0x989680;\n\t" \
            "@P1 bra.uni WAIT_DONE_%=;\n\t" \
            "bra.uni WAIT_LOOP_%=;\n\t" \
            "WAIT_DONE_%=:\n\t}" \
            :: "r"(_mbar), "r"(_parity) : "memory"); \
    } \
} while(0)

// ====================================================================
// scratch (no allocations allowed)
// ====================================================================
struct __align__(16) Scratch {
    __nv_bfloat16 w_in_b[FERD*FERD];
    __nv_bfloat16 w1_b  [1024*FERD];
    __nv_bfloat16 w2_b  [512*1024];
    __nv_bfloat16 xhi_fer[B_*FERD];
    __nv_bfloat16 xlo_fer[B_*FERD];
    __nv_bfloat16 l_win_b[LMD*LMD];
    __nv_bfloat16 l_w1_b [128*LMD];
    __nv_bfloat16 xhi_lm [B_*LMD];
    __nv_bfloat16 xlo_lm [B_*LMD];
    __nv_bfloat16 feats_fer_b[B_*FERD];
    __nv_bfloat16 feats_lm_b [B_*LMD];
    __nv_bfloat16 H_fer_b[NPAIR*1024];
    __nv_bfloat16 H_lm_b [NPAIR*128];
    __nv_bfloat16 l_w2_pad_b[128*128];
    float         l_b2_pad[128];
    float G_fer[B_*B_], P_fer[B_*B_];
    float G_lm [B_*B_], P_lm [B_*B_];
    float A_lm [B_*128],  Bm_lm [B_*128];
    float H2_lm [NPAIR*128];
    float score_fer[NPAIR], score_lm[NPAIR];
    int   nbr_fer[NPAIR], nbr_lm[NPAIR];
    float         CpartSim[16*B_*B_];      // sim partials (fp32 — topk fidelity)
    __nv_bfloat16 CpartH[2*1024*1024];     // FER-chain partials (bf16)
};
__device__ Scratch g_s;

// ====================================================================
// conversions split in two so only w_in + x precede the FER chain
// ====================================================================
#define CN1 (FERD*FERD)
#define CN2 (1024*FERD)
#define CN3 (512*1024)
#define CN4 (B_*FERD)
#define CN5 (LMD*LMD)
#define CN6 (128*LMD)
#define CN7 (B_*LMD)

__device__ __forceinline__ void cvt4(const float* src, __nv_bfloat16* dst,
                                     __nv_bfloat16* lo, int off) {
    float4 v = *(const float4*)(src + off);
    __nv_bfloat16 h0 = __float2bfloat16(v.x), h1 = __float2bfloat16(v.y);
    __nv_bfloat16 h2 = __float2bfloat16(v.z), h3 = __float2bfloat16(v.w);
    *(__nv_bfloat162*)(dst + off)     = __nv_bfloat162(h0, h1);
    *(__nv_bfloat162*)(dst + off + 2) = __nv_bfloat162(h2, h3);
    if (lo) {
        *(__nv_bfloat162*)(lo + off) = __nv_bfloat162(
            __float2bfloat16(v.x - __bfloat162float(h0)),
            __float2bfloat16(v.y - __bfloat162float(h1)));
        *(__nv_bfloat162*)(lo + off + 2) = __nv_bfloat162(
            __float2bfloat16(v.z - __bfloat162float(h2)),
            __float2bfloat16(v.w - __bfloat162float(h3)));
    }
}

__global__ void convertA(const float* __restrict__ fw_in, const float* __restrict__ fx,
                         const float* __restrict__ lx, Scratch* s) {
    int total4 = (CN1 + CN4 + CN7) / 4;
    for (int i = blockIdx.x * blockDim.x + threadIdx.x; i < total4;
         i += gridDim.x * blockDim.x) {
        int j = i * 4;
        if      (j < CN1)       cvt4(fw_in, s->w_in_b, nullptr, j);
        else if (j < CN1 + CN4) cvt4(fx, s->xhi_fer, s->xlo_fer, j - CN1);
        else                    cvt4(lx, s->xhi_lm, s->xlo_lm, j - CN1 - CN4);
    }
}

__global__ void convertB(const float* __restrict__ fw1, const float* __restrict__ fw2,
                         const float* __restrict__ lwin, const float* __restrict__ lw1,
                         const float* __restrict__ lw2, const float* __restrict__ lb2,
                         Scratch* s) {
    int total4 = (CN2 + CN3 + CN5 + CN6) / 4;
    for (int i = blockIdx.x * blockDim.x + threadIdx.x; i < total4;
         i += gridDim.x * blockDim.x) {
        int j = i * 4;
        if      (j < CN2)             cvt4(fw1, s->w1_b, nullptr, j);
        else if (j < CN2 + CN3)       cvt4(fw2, s->w2_b, nullptr, j - CN2);
        else if (j < CN2 + CN3 + CN5) cvt4(lwin, s->l_win_b, nullptr, j - CN2 - CN3);
        else                          cvt4(lw1, s->l_w1_b, nullptr, j - CN2 - CN3 - CN5);
    }
    int t = blockIdx.x * blockDim.x + threadIdx.x;
    if (t < 128 * 128) {
        int r = t >> 7, c = t & 127;
        s->l_w2_pad_b[t] = __float2bfloat16(r < 64 ? lw2[r * 128 + c] : 0.f);
    }
    if (t < 128) s->l_b2_pad[t] = (t < 64) ? lb2[t] : 0.f;
}

// ====================================================================
// bf16 HMMA GEMM, job-fusion (grid.z) + split-K partials.
// Partials: fp32 via Cpart (sim) OR bf16 via CpH (FER chain).
// Tile fill via cp.async.bulk + mbarrier complete_tx.
// ====================================================================
#define MM_LDS   72                      // elements; 144B row stride
#define MM_ATILE (128*MM_LDS*2)
#define MM_BUF   (2*MM_ATILE)
#define MM_SMEM  (128 + 3*MM_BUF)
#define MM_TX    (2*128*128)

__global__ void __launch_bounds__(256)
gemm_mma(const __nv_bfloat16* __restrict__ A0, const __nv_bfloat16* __restrict__ A1, int lda,
         const __nv_bfloat16* __restrict__ B0, const __nv_bfloat16* __restrict__ B1, int ldb,
         const float* __restrict__ bias, int relu,
         float* __restrict__ Cf0, float* __restrict__ Cf1,
         __nv_bfloat16* __restrict__ Cb0,
         float* __restrict__ Cpart, __nv_bfloat16* __restrict__ CpH,
         int njobs, int N, int K)
{
    extern __shared__ char smem[];
    uint32_t sb = smem_to_u32(smem);
    const uint32_t STG = sb + 128;
    int tid = threadIdx.x;
    int lane = tid & 31, warp = tid >> 5;
    int wm = warp >> 2, wn = warp & 3;
    int m0 = blockIdx.y * 128, n0 = blockIdx.x * 128;

    int z = blockIdx.z;
    int job   = (njobs == 2) ? (z & 1) : 0;
    int split = (njobs == 2) ? (z >> 1) : z;
    int nsplit = gridDim.z / njobs;
    int Ksplit = K / nsplit;
    int kbase = split * Ksplit;
    int nk = Ksplit >> 6;

    const __nv_bfloat16* A = job ? A1 : A0;
    const __nv_bfloat16* B = job ? B1 : B0;

    if (tid < 3) MBARRIER_INIT(sb + tid * 8, 1);
    __syncthreads();

    int rowi = tid & 127;
    int isB  = tid >> 7;
    const __nv_bfloat16* rowp = (isB ? B : A) +
        (size_t)((isB ? n0 : m0) + rowi) * (isB ? ldb : lda) + kbase;
    uint32_t dstoff = (uint32_t)(isB * MM_ATILE + rowi * (MM_LDS * 2));

    float acc[4][4][4];
    #pragma unroll
    for (int i = 0; i < 4; i++)
        #pragma unroll
        for (int j = 0; j < 4; j++)
            #pragma unroll
            for (int q = 0; q < 4; q++) acc[i][j][q] = 0.f;

    auto issue = [&](int kt) {
        int st = kt % 3;
        if (tid == 0) MBARRIER_EXPECT_TX(sb + st * 8, MM_TX);
        const __nv_bfloat16* src = rowp + kt * 64;
        asm volatile(
            "cp.async.bulk.shared::cluster.global.mbarrier::complete_tx::bytes "
            "[%0], [%1], 128, [%2];"
            :: "r"(STG + st * MM_BUF + dstoff), "l"(src), "r"(sb + st * 8)
            : "memory");
    };

    issue(0);
    if (nk > 1) issue(1);
    if (nk > 2) issue(2);
    for (int kt = 0; kt < nk; kt++) {
        int st = kt % 3;
        int par = (kt / 3) & 1;
        MBARRIER_WAIT_PARITY(sb + st * 8, par);

        uint32_t aBase = STG + st * MM_BUF;
        uint32_t bBase = aBase + MM_ATILE;
        #pragma unroll
        for (int ks = 0; ks < 4; ks++) {
            int k = ks * 16;
            uint32_t af[4][4];
            #pragma unroll
            for (int im = 0; im < 4; im++) {
                int row = wm * 64 + im * 16 + (lane & 15);
                int kg = (lane >> 4) * 8;
                uint32_t addr = aBase + (uint32_t)(row * MM_LDS + k + kg) * 2;
                asm volatile("ldmatrix.sync.aligned.m8n8.x4.shared.b16 {%0,%1,%2,%3}, [%4];"
                             : "=r"(af[im][0]), "=r"(af[im][1]),
                               "=r"(af[im][2]), "=r"(af[im][3])
                             : "r"(addr));
            }
            uint32_t bf[4][2];
            #pragma unroll
            for (int in = 0; in < 4; in++) {
                int l = lane & 15;
                int n = wn * 32 + in * 8 + (l & 7);
                int kg = (l >> 3) * 8;
                uint32_t addr = bBase + (uint32_t)(n * MM_LDS + k + kg) * 2;
                asm volatile("ldmatrix.sync.aligned.m8n8.x2.shared.b16 {%0,%1}, [%2];"
                             : "=r"(bf[in][0]), "=r"(bf[in][1])
                             : "r"(addr));
            }
            #pragma unroll
            for (int im = 0; im < 4; im++)
                #pragma unroll
                for (int in = 0; in < 4; in++) {
                    asm volatile(
                        "mma.sync.aligned.m16n8k16.row.col.f32.bf16.bf16.f32 "
                        "{%0,%1,%2,%3}, {%4,%5,%6,%7}, {%8,%9}, {%0,%1,%2,%3};"
                        : "+f"(acc[im][in][0]), "+f"(acc[im][in][1]),
                          "+f"(acc[im][in][2]), "+f"(acc[im][in][3])
                        : "r"(af[im][0]), "r"(af[im][1]), "r"(af[im][2]), "r"(af[im][3]),
                          "r"(bf[in][0]), "r"(bf[in][1]));
                }
        }
        __syncthreads();
        if (kt + 3 < nk) issue(kt + 3);
    }

    if (Cpart) {          // fp32 partials (sim chain)
        size_t MN = (size_t)gridDim.y * 128 * N;
        float* cp = Cpart + (size_t)z * MN;
        #pragma unroll
        for (int im = 0; im < 4; im++) {
            int m = m0 + wm * 64 + im * 16 + (lane >> 2);
            #pragma unroll
            for (int in = 0; in < 4; in++) {
                int n = n0 + wn * 32 + in * 8 + (lane & 3) * 2;
                *(float2*)(cp + (size_t)m * N + n) =
                    make_float2(acc[im][in][0], acc[im][in][1]);
                *(float2*)(cp + (size_t)(m + 8) * N + n) =
                    make_float2(acc[im][in][2], acc[im][in][3]);
            }
        }
        return;
    }
    if (CpH) {            // bf16 partials (FER chain)
        size_t MN = (size_t)gridDim.y * 128 * N;
        __nv_bfloat16* cp = CpH + (size_t)z * MN;
        #pragma unroll
        for (int im = 0; im < 4; im++) {
            int m = m0 + wm * 64 + im * 16 + (lane >> 2);
            #pragma unroll
            for (int in = 0; in < 4; in++) {
                int n = n0 + wn * 32 + in * 8 + (lane & 3) * 2;
                *(__nv_bfloat162*)(cp + (size_t)m * N + n) =
                    __floats2bfloat162_rn(acc[im][in][0], acc[im][in][1]);
                *(__nv_bfloat162*)(cp + (size_t)(m + 8) * N + n) =
                    __floats2bfloat162_rn(acc[im][in][2], acc[im][in][3]);
            }
        }
        return;
    }
    float* Cf = job ? Cf1 : Cf0;
    #pragma unroll
    for (int im = 0; im < 4; im++) {
        int m = m0 + wm * 64 + im * 16 + (lane >> 2);
        #pragma unroll
        for (int in = 0; in < 4; in++) {
            int n = n0 + wn * 32 + in * 8 + (lane & 3) * 2;
            float b0 = bias ? bias[n]     : 0.f;
            float b1 = bias ? bias[n + 1] : 0.f;
            float v00 = acc[im][in][0] + b0, v01 = acc[im][in][1] + b1;
            float v10 = acc[im][in][2] + b0, v11 = acc[im][in][3] + b1;
            if (relu) {
                v00 = fmaxf(v00, 0.f); v01 = fmaxf(v01, 0.f);
                v10 = fmaxf(v10, 0.f); v11 = fmaxf(v11, 0.f);
            }
            if (Cb0) {
                *(__nv_bfloat162*)(Cb0 + (size_t)m * N + n) =
                    __floats2bfloat162_rn(v00, v01);
                *(__nv_bfloat162*)(Cb0 + (size_t)(m + 8) * N + n) =
                    __floats2bfloat162_rn(v10, v11);
            } else {
                *(float2*)(Cf + (size_t)m * N + n)       = make_float2(v00, v01);
                *(float2*)(Cf + (size_t)(m + 8) * N + n) = make_float2(v10, v11);
            }
        }
    }
}

// ====================================================================
// fp32 split-K reduce (sim chain only)
// ====================================================================
__global__ void reduce_parts(const float* __restrict__ part, int nsplit, int njobs,
                             long MN, int N,
                             float* __restrict__ of0, float* __restrict__ of1) {
    long MN4 = MN >> 2;
    long total = (long)njobs * MN4;
    for (long idx = blockIdx.x * (long)blockDim.x + threadIdx.x; idx < total;
         idx += (long)gridDim.x * blockDim.x) {
        int  job = (int)(idx / MN4);
        long e4  = idx - (long)job * MN4;
        float4 acc[8];
        #pragma unroll
        for (int sp = 0; sp < 8; sp++) {
            acc[sp] = make_float4(0.f, 0.f, 0.f, 0.f);
            if (sp < nsplit)
                acc[sp] = *((const float4*)(part + ((size_t)(sp * njobs + job)) * MN) + e4);
        }
        float4 s;
        s.x = ((acc[0].x + acc[1].x) + (acc[2].x + acc[3].x)) +
              ((acc[4].x + acc[5].x) + (acc[6].x + acc[7].x));
        s.y = ((acc[0].y + acc[1].y) + (acc[2].y + acc[3].y)) +
              ((acc[4].y + acc[5].y) + (acc[6].y + acc[7].y));
        s.z = ((acc[0].z + acc[1].z) + (acc[2].z + acc[3].z)) +
              ((acc[4].z + acc[5].z) + (acc[6].z + acc[7].z));
        s.w = ((acc[0].w + acc[1].w) + (acc[2].w + acc[3].w)) +
              ((acc[4].w + acc[5].w) + (acc[6].w + acc[7].w));
        float* o = job ? of1 : of0;
        *((float4*)o + e4) = s;
    }
}

// ====================================================================
// bf16 split-K reduce for feats: 4 partials + bias -> bf16
// ====================================================================
__global__ void reduce_feats(const __nv_bfloat16* __restrict__ part,
                             const float* __restrict__ bias, int N,
                             __nv_bfloat16* __restrict__ ob) {
    const long MN = (long)B_ * FERD;
    long total4 = MN >> 2;
    for (long idx = blockIdx.x * (long)blockDim.x + threadIdx.x; idx < total4;
         idx += (long)gridDim.x * blockDim.x) {
        long e = idx * 4;
        float v[4] = {0.f, 0.f, 0.f, 0.f};
        #pragma unroll
        for (int sp = 0; sp < 4; sp++) {
            const __nv_bfloat162* p = (const __nv_bfloat162*)(part + sp * MN + e);
            __nv_bfloat162 p0 = p[0], p1 = p[1];
            v[0] += __bfloat162float(p0.x); v[1] += __bfloat162float(p0.y);
            v[2] += __bfloat162float(p1.x); v[3] += __bfloat162float(p1.y);
        }
        int col = (int)(e % N);
        v[0] += bias[col]; v[1] += bias[col + 1]; v[2] += bias[col + 2]; v[3] += bias[col + 3];
        *(__nv_bfloat162*)(ob + e)     = __floats2bfloat162_rn(v[0], v[1]);
        *(__nv_bfloat162*)(ob + e + 2) = __floats2bfloat162_rn(v[2], v[3]);
    }
}

// ====================================================================
// top-8: 512 warps; warp<256 -> FER matrices, else LM
// ====================================================================
__global__ void topk8_warp(const float* __restrict__ Gf, const float* __restrict__ Pf,
                           int* __restrict__ nbrf,
                           const float* __restrict__ Gl, const float* __restrict__ Pl,
                           int* __restrict__ nbrl) {
    int w = blockIdx.x * (blockDim.x >> 5) + (threadIdx.x >> 5);
    int lane = threadIdx.x & 31;
    const float* G; const float* P; int* nbr; int row;
    if (w < B_) { G = Gf; P = Pf; nbr = nbrf; row = w; }
    else        { G = Gl; P = Pl; nbr = nbrl; row = w - B_; }
    float v[8];
    #pragma unroll
    for (int t = 0; t < 8; t++) {
        int j = lane + t * 32;
        if (j == row) { v[t] = -1e30f; continue; }
        float g  = G[(size_t)row * B_ + j];
        float p1 = P[(size_t)row * B_ + j];
        float p2 = P[(size_t)j * B_ + row];
        float dg = G[(size_t)j * B_ + j];
        float dp = P[(size_t)j * B_ + j];
        v[t] = (g + p1 + p2) * rsqrtf(dg + 2.f * dp);
    }
    for (int t = 0; t < KNN; t++) {
        float bv = -1e30f; int bi = 0x7fffffff;
        #pragma unroll
        for (int q = 0; q < 8; q++) {
            int j = lane + q * 32;
            if (v[q] > bv || (v[q] == bv && j < bi)) { bv = v[q]; bi = j; }
        }
        #pragma unroll
        for (int o = 16; o; o >>= 1) {
            float ov = __shfl_xor_sync(0xffffffffu, bv, o);
            int   oi = __shfl_xor_sync(0xffffffffu, bi, o);
            if (ov > bv || (ov == bv && oi < bi)) { bv = ov; bi = oi; }
        }
        if (lane == 0) nbr[row * KNN + t] = bi;
        if (lane == (bi & 31)) v[bi >> 5] = -1e30f;
    }
}

// ====================================================================
// build H (FER: sums bf16 A/Bm partials; LM: direct fp32)
// ====================================================================
__global__ void build_h_all(const __nv_bfloat16* __restrict__ part,
                            const float* __restrict__ f_b1,
                            const int* __restrict__ nbrf, __nv_bfloat16* __restrict__ Hf,
                            const float* __restrict__ A_lm, const float* __restrict__ Bm_lm,
                            const float* __restrict__ l_b1, const int* __restrict__ nbrl,
                            __nv_bfloat16* __restrict__ Hl) {
    int blk = blockIdx.x;
    if (blk < NPAIR) {
        const long MN = (long)B_ * 1024;
        int pair = blk;
        int i = pair >> 3;
        int j = nbrf[pair];
        int k = threadIdx.x * 4;
        const __nv_bfloat162* a0 = (const __nv_bfloat162*)(part + 0 * MN + (size_t)i * 1024 + k);
        const __nv_bfloat162* a1 = (const __nv_bfloat162*)(part + 2 * MN + (size_t)i * 1024 + k);
        const __nv_bfloat162* b0 = (const __nv_bfloat162*)(part + 1 * MN + (size_t)j * 1024 + k);
        const __nv_bfloat162* b1 = (const __nv_bfloat162*)(part + 3 * MN + (size_t)j * 1024 + k);
        __nv_bfloat162 a00 = a0[0], a01 = a0[1];
        __nv_bfloat162 a10 = a1[0], a11 = a1[1];
        __nv_bfloat162 b00 = b0[0], b01 = b0[1];
        __nv_bfloat162 b10 = b1[0], b11 = b1[1];
        float4 bb = *(const float4*)(f_b1 + k);
        float h0 = fmaxf(__bfloat162float(a00.x) + __bfloat162float(a10.x) +
                         __bfloat162float(b00.x) + __bfloat162float(b10.x) + bb.x, 0.f);
        float h1 = fmaxf(__bfloat162float(a00.y) + __bfloat162float(a10.y) +
                         __bfloat162float(b00.y) + __bfloat162float(b10.y) + bb.y, 0.f);
        float h2 = fmaxf(__bfloat162float(a01.x) + __bfloat162float(a11.x) +
                         __bfloat162float(b01.x) + __bfloat162float(b11.x) + bb.z, 0.f);
        float h3 = fmaxf(__bfloat162float(a01.y) + __bfloat162float(a11.y) +
                         __bfloat162float(b01.y) + __bfloat162float(b11.y) + bb.w, 0.f);
        __nv_bfloat16* hr = Hf + (size_t)pair * 1024 + k;
        *(__nv_bfloat162*)(hr)     = __floats2bfloat162_rn(h0, h1);
        *(__nv_bfloat162*)(hr + 2) = __floats2bfloat162_rn(h2, h3);
    } else {
        int pair = blk - NPAIR;
        int i = pair >> 3;
        int j = nbrl[pair];
        int t = threadIdx.x;
        if (t < 32) {
            int k = t * 4;
            float4 va = *(const float4*)(A_lm + (size_t)i * 128 + k);
            float4 vb = *(const float4*)(Bm_lm + (size_t)j * 128 + k);
            float4 bb = *(const float4*)(l_b1 + k);
            float h0 = fmaxf(va.x + vb.x + bb.x, 0.f);
            float h1 = fmaxf(va.y + vb.y + bb.y, 0.f);
            float h2 = fmaxf(va.z + vb.z + bb.z, 0.f);
            float h3 = fmaxf(va.w + vb.w + bb.w, 0.f);
            __nv_bfloat16* hr = Hl + (size_t)pair * 128 + k;
            *(__nv_bfloat162*)(hr)     = __floats2bfloat162_rn(h0, h1);
            *(__nv_bfloat162*)(hr + 2) = __floats2bfloat162_rn(h2, h3);
        }
    }
}

// ====================================================================
// fused score (FER: sums bf16 H2 partials inline; LM: direct)
// ====================================================================
__global__ void score_fused(const __nv_bfloat16* __restrict__ fpart,
                            const float* __restrict__ f_b2,
                            const float* __restrict__ f_w3, const float* __restrict__ f_b3,
                            float* __restrict__ sf,
                            const float* __restrict__ lH2, const float* __restrict__ l_w3,
                            const float* __restrict__ l_b3, float* __restrict__ sl) {
    int w = blockIdx.x * (blockDim.x >> 5) + (threadIdx.x >> 5);
    int lane = threadIdx.x & 31;
    float s = 0.f;
    if (w < NPAIR) {
        const long MN = (long)NPAIR * 512;
        const __nv_bfloat16* h0 = fpart + (size_t)w * 512;
        const __nv_bfloat16* h1 = fpart + MN + (size_t)w * 512;
        #pragma unroll
        for (int q = 0; q < 8; q++) {
            int k = lane * 2 + q * 64;
            __nv_bfloat162 p0 = *(const __nv_bfloat162*)(h0 + k);
            __nv_bfloat162 p1 = *(const __nv_bfloat162*)(h1 + k);
            float ha = fmaxf(__bfloat162float(p0.x) + __bfloat162float(p1.x) + f_b2[k], 0.f);
            float hb = fmaxf(__bfloat162float(p0.y) + __bfloat162float(p1.y) + f_b2[k + 1], 0.f);
            s += ha * (f_w3[k] - f_w3[512 + k]);
            s += hb * (f_w3[k + 1] - f_w3[512 + k + 1]);
        }
        #pragma unroll
        for (int o = 16; o; o >>= 1) s += __shfl_xor_sync(0xffffffffu, s, o);
        if (lane == 0) {
            s += f_b3[0] - f_b3[1];
            sf[w] = 1.f / (1.f + expf(-s));
        }
    } else {
        int pair = w - NPAIR;
        const float* h = lH2 + (size_t)pair * 128;
        #pragma unroll
        for (int q = 0; q < 2; q++) {
            int k = lane + q * 32;
            s += h[k] * (l_w3[k] - l_w3[64 + k]);
        }
        #pragma unroll
        for (int o = 16; o; o >>= 1) s += __shfl_xor_sync(0xffffffffu, s, o);
        if (lane == 0) {
            s += l_b3[0] - l_b3[1];
            sl[pair] = 1.f / (1.f + expf(-s));
        }
    }
}

// ====================================================================
// softmax(logits), normalize weights, combine with bank
// ====================================================================
__global__ void combine(const float* __restrict__ logits, const int* __restrict__ idx,
                        const float* __restrict__ bank,
                        const float* __restrict__ sf, const float* __restrict__ sl,
                        const int* __restrict__ nbrf, const int* __restrict__ nbrl,
                        float* __restrict__ out) {
    __shared__ float p[B_][NC];
    __shared__ float colsum[NC];
    int i = threadIdx.x;
    const float* lr = logits + i * NC;
    float m = lr[0];
    #pragma unroll
    for (int c = 1; c < NC; c++) m = fmaxf(m, lr[c]);
    float e[NC]; float ssum = 0.f;
    #pragma unroll
    for (int c = 0; c < NC; c++) { e[c] = expf(lr[c] - m); ssum += e[c]; }
    float invs = 1.f / ssum;
    #pragma unroll
    for (int c = 0; c < NC; c++) p[i][c] = e[c] * invs;
    __syncthreads();
    if (i < NC) {
        float s = 0.f;
        for (int r = 0; r < B_; r++) s += p[r][i];
        colsum[i] = s;
    }
    __syncthreads();
    float Sf = 0.f, Sl = 0.f;
    #pragma unroll
    for (int t = 0; t < KNN; t++) { Sf += sf[i * KNN + t]; Sl += sl[i * KNN + t]; }
    float df = 1.f / (Sf + EPSV), dl = 1.f / (Sl + EPSV);
    float tf[NC], tl[NC];
    #pragma unroll
    for (int c = 0; c < NC; c++) { tf[c] = 0.f; tl[c] = 0.f; }
    #pragma unroll
    for (int t = 0; t < KNN; t++) {
        int jf = nbrf[i * KNN + t]; float wf = sf[i * KNN + t] * df;
        int jl = nbrl[i * KNN + t]; float wl = sl[i * KNN + t] * dl;
        #pragma unroll
        for (int c = 0; c < NC; c++) {
            tf[c] += wf * p[jf][c];
            tl[c] += wl * p[jl][c];
        }
    }
    float ef = (EPSV / (float)B_) * df;
    float el = (EPSV / (float)B_) * dl;
    #pragma unroll
    for (int c = 0; c < NC; c++) {
        float tgt = 0.5f * (tf[c] + ef * colsum[c]) + 0.5f * (tl[c] + el * colsum[c]);
        out[i * NC + c] = bank[(size_t)idx[i] * NC + c] * 0.9f + tgt * 0.1f;
    }
}

// ====================================================================
// launcher — fork/join DAG (graph-capturable)
// ====================================================================
extern "C" void kernel_launch(void* const* d_in, const int* in_sizes, int n_in,
                              void* d_out, int out_size) {
    const float* fer_x  = (const float*)d_in[0];
    const float* lm_x   = (const float*)d_in[1];
    const float* logits = (const float*)d_in[2];
    const int*   idx    = (const int*)  d_in[3];
    const float* bank   = (const float*)d_in[4];
    const float* f_win  = (const float*)d_in[5];
    const float* f_bin  = (const float*)d_in[6];
    const float* f_w1   = (const float*)d_in[7];
    const float* f_b1   = (const float*)d_in[8];
    const float* f_w2   = (const float*)d_in[9];
    const float* f_b2   = (const float*)d_in[10];
    const float* f_w3   = (const float*)d_in[11];
    const float* f_b3   = (const float*)d_in[12];
    const float* l_win  = (const float*)d_in[13];
    const float* l_bin  = (const float*)d_in[14];
    const float* l_w1   = (const float*)d_in[15];
    const float* l_b1   = (const float*)d_in[16];
    const float* l_w2   = (const float*)d_in[17];
    const float* l_b2   = (const float*)d_in[18];
    const float* l_w3   = (const float*)d_in[19];
    const float* l_b3   = (const float*)d_in[20];
    float* out = (float*)d_out;

    Scratch* s = nullptr;
    cudaGetSymbolAddress((void**)&s, g_s);
    if (!s) return;

    struct Res {
        cudaStream_t s1, s2, s3;
        cudaEvent_t eR, e0, eW, eS2, eT, eL3, eBH, eLH;
        Res() {
            cudaStreamCreateWithFlags(&s1, cudaStreamNonBlocking);
            cudaStreamCreateWithFlags(&s2, cudaStreamNonBlocking);
            cudaStreamCreateWithFlags(&s3, cudaStreamNonBlocking);
            cudaEventCreateWithFlags(&eR,  cudaEventDisableTiming);
            cudaEventCreateWithFlags(&e0,  cudaEventDisableTiming);
            cudaEventCreateWithFlags(&eW,  cudaEventDisableTiming);
            cudaEventCreateWithFlags(&eS2, cudaEventDisableTiming);
            cudaEventCreateWithFlags(&eT,  cudaEventDisableTiming);
            cudaEventCreateWithFlags(&eL3, cudaEventDisableTiming);
            cudaEventCreateWithFlags(&eBH, cudaEventDisableTiming);
            cudaEventCreateWithFlags(&eLH, cudaEventDisableTiming);
            cudaFuncSetAttribute(gemm_mma,
                cudaFuncAttributeMaxDynamicSharedMemorySize, MM_SMEM);
        }
    };
    static Res r;
    cudaStream_t L = 0;

    // capture-root fork for s2
    cudaEventRecord(r.eR, L);
    cudaStreamWaitEvent(r.s2, r.eR, 0);
    convertB<<<256, 256, 0, r.s2>>>(f_w1, f_w2, l_win, l_w1, l_w2, l_b2, s);
    cudaEventRecord(r.eW, r.s2);

    convertA<<<512, 256, 0, L>>>(f_win, fer_x, lm_x, s);
    cudaEventRecord(r.e0, L);

    // s1: FER sim -> reduce -> (wait LM sim) -> topk
    cudaStreamWaitEvent(r.s1, r.e0, 0);
    gemm_mma<<<dim3(2, 2, 16), 256, MM_SMEM, r.s1>>>(
        s->xhi_fer, s->xhi_fer, FERD, s->xhi_fer, s->xlo_fer, FERD,
        nullptr, 0, nullptr, nullptr, nullptr, s->CpartSim, nullptr, 2, B_, FERD);
    reduce_parts<<<256, 256, 0, r.s1>>>(s->CpartSim, 8, 2, (long)B_ * B_, B_,
                                        s->G_fer, s->P_fer);
    // s2: LM sim
    cudaStreamWaitEvent(r.s2, r.e0, 0);
    gemm_mma<<<dim3(2, 2, 2), 256, MM_SMEM, r.s2>>>(
        s->xhi_lm, s->xhi_lm, LMD, s->xhi_lm, s->xlo_lm, LMD,
        nullptr, 0, s->G_lm, s->P_lm, nullptr, nullptr, nullptr, 2, B_, LMD);
    cudaEventRecord(r.eS2, r.s2);
    cudaStreamWaitEvent(r.s1, r.eS2, 0);
    topk8_warp<<<64, 256, 0, r.s1>>>(s->G_fer, s->P_fer, s->nbr_fer,
                                     s->G_lm, s->P_lm, s->nbr_lm);
    cudaEventRecord(r.eT, r.s1);

    // s3: LM MLP
    cudaStreamWaitEvent(r.s3, r.e0, 0);
    cudaStreamWaitEvent(r.s3, r.eW, 0);
    gemm_mma<<<dim3(LMD/128, B_/128, 1), 256, MM_SMEM, r.s3>>>(
        s->xhi_lm, nullptr, LMD, s->l_win_b, nullptr, LMD,
        l_bin, 0, nullptr, nullptr, s->feats_lm_b, nullptr, nullptr, 1, LMD, LMD);
    gemm_mma<<<dim3(1, B_/128, 2), 256, MM_SMEM, r.s3>>>(
        s->feats_lm_b, s->feats_lm_b + 128, LMD, s->l_w1_b, s->l_w1_b + 128, LMD,
        nullptr, 0, s->A_lm, s->Bm_lm, nullptr, nullptr, nullptr, 2, 128, 128);
    cudaEventRecord(r.eL3, r.s3);

    // L: FER MLP (feats -> reduce -> [wait w1] A/Bm) — bf16 partials
    gemm_mma<<<dim3(FERD/128, B_/128, 4), 256, MM_SMEM, L>>>(
        s->xhi_fer, nullptr, FERD, s->w_in_b, nullptr, FERD,
        nullptr, 0, nullptr, nullptr, nullptr, nullptr, s->CpartH, 1, FERD, FERD);
    reduce_feats<<<512, 256, 0, L>>>(s->CpartH, f_bin, FERD, s->feats_fer_b);
    cudaStreamWaitEvent(L, r.eW, 0);
    gemm_mma<<<dim3(1024/128, B_/128, 4), 256, MM_SMEM, L>>>(
        s->feats_fer_b, s->feats_fer_b + 1024, FERD, s->w1_b, s->w1_b + 1024, FERD,
        nullptr, 0, nullptr, nullptr, nullptr, nullptr, s->CpartH, 2, 1024, 1024);

    // join for build_h
    cudaStreamWaitEvent(L, r.eT, 0);
    cudaStreamWaitEvent(L, r.eL3, 0);
    build_h_all<<<2 * NPAIR, 256, 0, L>>>(s->CpartH, f_b1, s->nbr_fer, s->H_fer_b,
                                          s->A_lm, s->Bm_lm, l_b1, s->nbr_lm, s->H_lm_b);
    cudaEventRecord(r.eBH, L);

    // FER H2 (bf16 partials) on L; LM H2 on s3
    gemm_mma<<<dim3(512/128, NPAIR/128, 2), 256, MM_SMEM, L>>>(
        s->H_fer_b, nullptr, 1024, s->w2_b, nullptr, 1024,
        nullptr, 0, nullptr, nullptr, nullptr, nullptr, s->CpartH, 1, 512, 1024);
    cudaStreamWaitEvent(r.s3, r.eBH, 0);
    gemm_mma<<<dim3(1, NPAIR/128, 1), 256, MM_SMEM, r.s3>>>(
        s->H_lm_b, nullptr, 128, s->l_w2_pad_b, nullptr, 128,
        s->l_b2_pad, 1, s->H2_lm, nullptr, nullptr, nullptr, nullptr, 1, 128, 128);
    cudaEventRecord(r.eLH, r.s3);

    // score + combine
    cudaStreamWaitEvent(L, r.eLH, 0);
    score_fused<<<512, 256, 0, L>>>(s->CpartH, f_b2, f_w3, f_b3, s->score_fer,
                                    s->H2_lm, l_w3, l_b3, s->score_lm);
    combine<<<1, B_, 0, L>>>(logits, idx, bank, s->score_fer, s->score_lm,
                             s->nbr_fer, s->nbr_lm, out);
}